// round 8
// baseline (speedup 1.0000x reference)
#include <cuda_runtime.h>
#include <cuda_bf16.h>
#include <cstdint>

// Problem constants
#define TT   8192
#define NEXP 8
#define DIMC 1024
#define HIDC 2048

// Tiling: CTA 128x256, 8 math warps (2x4, warp tile 64x64) + 1 loader warp
#define BM      128
#define BN      256
#define BK      64
#define ROWB    144      // padded row stride (bytes) -> conflict-free ldmatrix
#define STAGES  3
#define NTHREADS 288     // 9 warps

static constexpr int A_BYTES     = BM * ROWB;            // 18432
static constexpr int B_BYTES     = BN * ROWB;            // 36864
static constexpr int STAGE_BYTES = A_BYTES + B_BYTES;    // 55296
static constexpr int SMEM_DYN    = STAGES * STAGE_BYTES; // 165888

// bf16 staging + intermediate
__device__ __nv_bfloat16 g_xb[(size_t)TT * DIMC];
__device__ __nv_bfloat16 g_w1b[(size_t)NEXP * HIDC * DIMC];
__device__ __nv_bfloat16 g_w2b[(size_t)NEXP * DIMC * HIDC];
__device__ __nv_bfloat16 g_hidden[(size_t)TT * HIDC];

static __device__ __forceinline__ uint32_t smem_u32(const void* p) {
    return (uint32_t)__cvta_generic_to_shared(p);
}
static __device__ __forceinline__ void cp16(uint32_t dst, const void* src) {
    asm volatile("cp.async.cg.shared.global [%0], [%1], 16;" :: "r"(dst), "l"(src));
}
static __device__ __forceinline__ void cp_commit() {
    asm volatile("cp.async.commit_group;" ::: "memory");
}
template <int N>
static __device__ __forceinline__ void cp_wait() {
    asm volatile("cp.async.wait_group %0;" :: "n"(N) : "memory");
}
static __device__ __forceinline__ void ldsm_x4(uint32_t* r, uint32_t addr) {
    asm volatile("ldmatrix.sync.aligned.m8n8.x4.shared.b16 {%0,%1,%2,%3}, [%4];"
                 : "=r"(r[0]), "=r"(r[1]), "=r"(r[2]), "=r"(r[3]) : "r"(addr));
}
static __device__ __forceinline__ void bar_sync(int id) {
    asm volatile("bar.sync %0, %1;" :: "r"(id), "n"(NTHREADS) : "memory");
}
static __device__ __forceinline__ void bar_arrive(int id) {
    asm volatile("bar.arrive %0, %1;" :: "r"(id), "n"(NTHREADS) : "memory");
}
// barrier ids: EMPTY(s) = 1+s, FULL(s) = 4+s   (s in 0..2)

// ---------------- fp32 -> bf16 pre-pass ----------------
__global__ void cvt_f32_bf16(const float4* __restrict__ in, uint2* __restrict__ out, int n4) {
    int i = blockIdx.x * blockDim.x + threadIdx.x;
    if (i < n4) {
        float4 v = in[i];
        __nv_bfloat162 lo = __floats2bfloat162_rn(v.x, v.y);
        __nv_bfloat162 hi = __floats2bfloat162_rn(v.z, v.w);
        out[i] = make_uint2(*reinterpret_cast<uint32_t*>(&lo),
                            *reinterpret_cast<uint32_t*>(&hi));
    }
}

// ---------------- grouped bf16 GEMM, warp-specialized producer/consumer ------
// C[m,n] = bf16_round( sum_k A[m,k] * B_e[n,k] ), rows m grouped by expert.
template <typename OT>
__global__ void __launch_bounds__(NTHREADS, 1)
gemm_grouped(const __nv_bfloat16* __restrict__ A, const __nv_bfloat16* __restrict__ Ball,
             OT* __restrict__ C, const int* __restrict__ counts, int K, int N) {
    extern __shared__ char smem[];

    const int tid  = threadIdx.x;
    const int lane = tid & 31;
    const int warp = tid >> 5;
    const bool is_loader = (warp == 8);
    const int m0 = blockIdx.x * BM;
    const int n0 = blockIdx.y * BN;
    const int wm = (warp >> 2) * 64;   // math warps 0..7: 2 rows x 4 cols
    const int wn = (warp & 3) * 64;
    const int ko = (warp & 1) << 1;    // ks-order stagger between warp halves

    const int nk = K / BK;
    const uint32_t sbase = smem_u32(smem);

    // ldmatrix fragment addressing
    const int fr = lane & 15;
    const int fc = ((lane >> 4) << 3) * 2;

    // Initialize pipeline: math threads pre-mark all stages EMPTY.
    if (!is_loader) {
        bar_arrive(1); bar_arrive(2); bar_arrive(3);
    }

    int off = 0;
    for (int e = 0; e < NEXP; ++e) {
        const int cnt = counts[e];
        const int s0 = off;
        off += cnt;
        const int lo = max(s0, m0), hi = min(off, m0 + BM);
        if (lo >= hi) continue;

        const __nv_bfloat16* B = Ball + (size_t)e * N * K;

        if (is_loader) {
            // ---------------- producer ----------------
            int fills = 0, fulls = 0;
            for (int kt = 0; kt < nk; ++kt) {
                const int s = fills % 3;
                bar_sync(1 + s);                       // wait stage EMPTY
                char* sA = smem + s * STAGE_BYTES;
                char* sB = sA + A_BYTES;
                #pragma unroll 4
                for (int c = lane; c < BM * 8; c += 32) {      // A: 1024 chunks
                    const int row = c >> 3, cc = c & 7;
                    cp16(smem_u32(sA + row * ROWB + cc * 16),
                         A + (size_t)(m0 + row) * K + kt * BK + cc * 8);
                }
                #pragma unroll 4
                for (int c = lane; c < BN * 8; c += 32) {      // B: 2048 chunks
                    const int row = c >> 3, cc = c & 7;
                    cp16(smem_u32(sB + row * ROWB + cc * 16),
                         B + (size_t)(n0 + row) * K + kt * BK + cc * 8);
                }
                cp_commit();
                ++fills;
                if (fills - fulls > 2) {
                    cp_wait<2>();                      // oldest in-flight landed
                    bar_arrive(4 + fulls % 3);         // signal FULL
                    ++fulls;
                }
            }
            cp_wait<1>(); bar_arrive(4 + fulls % 3); ++fulls;
            cp_wait<0>(); bar_arrive(4 + fulls % 3); ++fulls;
        } else {
            // ---------------- consumers ----------------
            float acc[4][8][4];
            #pragma unroll
            for (int mi = 0; mi < 4; ++mi)
                #pragma unroll
                for (int ni = 0; ni < 8; ++ni)
                    #pragma unroll
                    for (int r = 0; r < 4; ++r) acc[mi][ni][r] = 0.f;

            for (int kt = 0; kt < nk; ++kt) {
                const int s = kt % 3;
                bar_sync(4 + s);                       // wait stage FULL
                const uint32_t aS = sbase + s * STAGE_BYTES;
                const uint32_t bS = aS + A_BYTES;

                #pragma unroll
                for (int i = 0; i < BK / 16; ++i) {
                    const int ks = (i + ko) & 3;       // staggered order
                    const int kk = ks * 32;            // bytes
                    uint32_t a[4][4];
                    #pragma unroll
                    for (int mi = 0; mi < 4; ++mi)
                        ldsm_x4(a[mi], aS + (wm + mi * 16 + fr) * ROWB + kk + fc);
                    uint32_t b[4][4];
                    #pragma unroll
                    for (int nj = 0; nj < 4; ++nj)
                        ldsm_x4(b[nj], bS + (wn + nj * 16 + fr) * ROWB + kk + fc);
                    #pragma unroll
                    for (int mi = 0; mi < 4; ++mi)
                        #pragma unroll
                        for (int n8 = 0; n8 < 8; ++n8) {
                            const uint32_t b0 = b[n8 >> 1][n8 & 1];
                            const uint32_t b1 = b[n8 >> 1][(n8 & 1) + 2];
                            asm volatile(
                                "mma.sync.aligned.m16n8k16.row.col.f32.bf16.bf16.f32 "
                                "{%0,%1,%2,%3}, {%4,%5,%6,%7}, {%8,%9}, {%0,%1,%2,%3};"
                                : "+f"(acc[mi][n8][0]), "+f"(acc[mi][n8][1]),
                                  "+f"(acc[mi][n8][2]), "+f"(acc[mi][n8][3])
                                : "r"(a[mi][0]), "r"(a[mi][1]), "r"(a[mi][2]), "r"(a[mi][3]),
                                  "r"(b0), "r"(b1));
                        }
                }
                bar_arrive(1 + s);                     // mark stage EMPTY
            }

            // Epilogue: bf16-round (reference keeps bf16 after each dot), masked.
            #pragma unroll
            for (int mi = 0; mi < 4; ++mi) {
                const int r0 = m0 + wm + mi * 16 + (lane >> 2);
                const int r1 = r0 + 8;
                const bool ok0 = (r0 >= lo) && (r0 < hi);
                const bool ok1 = (r1 >= lo) && (r1 < hi);
                #pragma unroll
                for (int n8 = 0; n8 < 8; ++n8) {
                    const int col = n0 + wn + n8 * 8 + (lane & 3) * 2;
                    if (ok0) {
                        if constexpr (sizeof(OT) == 2) {
                            __nv_bfloat162 v = __floats2bfloat162_rn(acc[mi][n8][0], acc[mi][n8][1]);
                            *reinterpret_cast<__nv_bfloat162*>(C + (size_t)r0 * N + col) = v;
                        } else {
                            float2 v = make_float2(
                                __bfloat162float(__float2bfloat16(acc[mi][n8][0])),
                                __bfloat162float(__float2bfloat16(acc[mi][n8][1])));
                            *reinterpret_cast<float2*>(C + (size_t)r0 * N + col) = v;
                        }
                    }
                    if (ok1) {
                        if constexpr (sizeof(OT) == 2) {
                            __nv_bfloat162 v = __floats2bfloat162_rn(acc[mi][n8][2], acc[mi][n8][3]);
                            *reinterpret_cast<__nv_bfloat162*>(C + (size_t)r1 * N + col) = v;
                        } else {
                            float2 v = make_float2(
                                __bfloat162float(__float2bfloat16(acc[mi][n8][2])),
                                __bfloat162float(__float2bfloat16(acc[mi][n8][3])));
                            *reinterpret_cast<float2*>(C + (size_t)r1 * N + col) = v;
                        }
                    }
                }
            }
        }
    }
}

extern "C" void kernel_launch(void* const* d_in, const int* in_sizes, int n_in,
                              void* d_out, int out_size) {
    const float* x      = (const float*)d_in[0];   // [TT, DIMC]
    const float* w1     = (const float*)d_in[1];   // [NEXP, HIDC, DIMC]
    const float* w2     = (const float*)d_in[2];   // [NEXP, DIMC, HIDC]
    const int*   counts = (const int*)d_in[3];     // [NEXP]
    float*       out    = (float*)d_out;           // [TT, DIMC]

    void *xb, *w1b, *w2b, *hb;
    cudaGetSymbolAddress(&xb,  g_xb);
    cudaGetSymbolAddress(&w1b, g_w1b);
    cudaGetSymbolAddress(&w2b, g_w2b);
    cudaGetSymbolAddress(&hb,  g_hidden);

    cudaFuncSetAttribute(gemm_grouped<__nv_bfloat16>,
                         cudaFuncAttributeMaxDynamicSharedMemorySize, SMEM_DYN);
    cudaFuncSetAttribute(gemm_grouped<float>,
                         cudaFuncAttributeMaxDynamicSharedMemorySize, SMEM_DYN);

    // fp32 -> bf16 conversions
    {
        int n4x = TT * DIMC / 4;
        cvt_f32_bf16<<<(n4x + 255) / 256, 256>>>((const float4*)x, (uint2*)xb, n4x);
        int n4w = NEXP * HIDC * DIMC / 4;
        cvt_f32_bf16<<<(n4w + 255) / 256, 256>>>((const float4*)w1, (uint2*)w1b, n4w);
        cvt_f32_bf16<<<(n4w + 255) / 256, 256>>>((const float4*)w2, (uint2*)w2b, n4w);
    }

    // GEMM1: hidden[T, HID] = x_bf16 @ w1[e]^T   (bf16 out)
    gemm_grouped<__nv_bfloat16><<<dim3(TT / BM, HIDC / BN), NTHREADS, SMEM_DYN>>>(
        (const __nv_bfloat16*)xb, (const __nv_bfloat16*)w1b,
        (__nv_bfloat16*)hb, counts, DIMC, HIDC);
    // GEMM2: out[T, DIM] = hidden @ w2[e]^T   (bf16-rounded fp32 out)
    gemm_grouped<float><<<dim3(TT / BM, DIMC / BN), NTHREADS, SMEM_DYN>>>(
        (const __nv_bfloat16*)hb, (const __nv_bfloat16*)w2b,
        out, counts, HIDC, DIMC);
}

// round 9
// speedup vs baseline: 1.7337x; 1.7337x over previous
#include <cuda_runtime.h>
#include <cuda_bf16.h>
#include <cstdint>

// Problem constants
#define TT   8192
#define NEXP 8
#define DIMC 1024
#define HIDC 2048

// Tiling: CTA 128x128, 4 warps (2x2), warp tile 64x64, 2 CTAs/SM, persistent
#define BM      128
#define BN      128
#define BK      64
#define ROWB    144      // padded row stride in bytes (72 bf16) -> conflict-free
#define STAGES  3

static constexpr int A_BYTES     = BM * ROWB;          // 18432
static constexpr int B_BYTES     = BN * ROWB;          // 18432
static constexpr int STAGE_BYTES = A_BYTES + B_BYTES;  // 36864
static constexpr int SMEM_DYN    = STAGES * STAGE_BYTES;  // 110592 (x2 CTAs = 221KB)

// bf16 staging + intermediate
__device__ __nv_bfloat16 g_xb[(size_t)TT * DIMC];
__device__ __nv_bfloat16 g_w1b[(size_t)NEXP * HIDC * DIMC];
__device__ __nv_bfloat16 g_w2b[(size_t)NEXP * DIMC * HIDC];
__device__ __nv_bfloat16 g_hidden[(size_t)TT * HIDC];

static __device__ __forceinline__ uint32_t smem_u32(const void* p) {
    return (uint32_t)__cvta_generic_to_shared(p);
}
static __device__ __forceinline__ void cp16(uint32_t dst, const void* src) {
    asm volatile("cp.async.cg.shared.global [%0], [%1], 16;" :: "r"(dst), "l"(src));
}
static __device__ __forceinline__ void cp_commit() {
    asm volatile("cp.async.commit_group;" ::: "memory");
}
template <int N>
static __device__ __forceinline__ void cp_wait() {
    asm volatile("cp.async.wait_group %0;" :: "n"(N) : "memory");
}
static __device__ __forceinline__ void ldsm_x4(uint32_t* r, uint32_t addr) {
    asm volatile("ldmatrix.sync.aligned.m8n8.x4.shared.b16 {%0,%1,%2,%3}, [%4];"
                 : "=r"(r[0]), "=r"(r[1]), "=r"(r[2]), "=r"(r[3]) : "r"(addr));
}

// ---------------- merged fp32 -> bf16 pre-pass (persistent grid-stride) ------
__global__ void cvt_all(const float4* __restrict__ x,  uint2* __restrict__ xo,  int nx,
                        const float4* __restrict__ w1, uint2* __restrict__ w1o, int nw,
                        const float4* __restrict__ w2, uint2* __restrict__ w2o) {
    const int stride = gridDim.x * blockDim.x;
    int i0 = blockIdx.x * blockDim.x + threadIdx.x;
    for (int i = i0; i < nx; i += stride) {
        float4 v = x[i];
        __nv_bfloat162 lo = __floats2bfloat162_rn(v.x, v.y);
        __nv_bfloat162 hi = __floats2bfloat162_rn(v.z, v.w);
        xo[i] = make_uint2(*reinterpret_cast<uint32_t*>(&lo), *reinterpret_cast<uint32_t*>(&hi));
    }
    for (int i = i0; i < nw; i += stride) {
        float4 v = w1[i];
        __nv_bfloat162 lo = __floats2bfloat162_rn(v.x, v.y);
        __nv_bfloat162 hi = __floats2bfloat162_rn(v.z, v.w);
        w1o[i] = make_uint2(*reinterpret_cast<uint32_t*>(&lo), *reinterpret_cast<uint32_t*>(&hi));
    }
    for (int i = i0; i < nw; i += stride) {
        float4 v = w2[i];
        __nv_bfloat162 lo = __floats2bfloat162_rn(v.x, v.y);
        __nv_bfloat162 hi = __floats2bfloat162_rn(v.z, v.w);
        w2o[i] = make_uint2(*reinterpret_cast<uint32_t*>(&lo), *reinterpret_cast<uint32_t*>(&hi));
    }
}

// ---------------- grouped bf16 GEMM (persistent, cp.async + mma.sync) --------
// C[m,n] = bf16_round( sum_k A[m,k] * B_e[n,k] ), rows m grouped by expert.
// Tiles: t -> m-tile = t % MT (fastest, so concurrent CTAs share weight tiles),
//             n-tile = t / MT.
template <typename OT>
__global__ void __launch_bounds__(128, 2)
gemm_grouped(const __nv_bfloat16* __restrict__ A, const __nv_bfloat16* __restrict__ Ball,
             OT* __restrict__ C, const int* __restrict__ counts, int K, int N,
             int MT, int NT) {
    extern __shared__ char smem[];

    const int tid  = threadIdx.x;
    const int lane = tid & 31;
    const int warp = tid >> 5;
    const int wm = (warp >> 1) * 64;   // 2 warp-rows
    const int wn = (warp & 1) * 64;    // 2 warp-cols

    const int nk = K / BK;

    // ldmatrix fragment addressing
    const int fr = lane & 15;                 // row within 16
    const int fc = ((lane >> 4) << 3) * 2;    // 0 or 16 bytes (k half)
    const uint32_t sbase = smem_u32(smem);

    for (int t = blockIdx.x; t < NT; t += gridDim.x) {
        const int m0 = (t % MT) * BM;
        const int n0 = (t / MT) * BN;

        int off = 0;
        for (int e = 0; e < NEXP; ++e) {
            const int cnt = counts[e];
            const int s0 = off;
            off += cnt;
            const int lo = max(s0, m0), hi = min(off, m0 + BM);
            if (lo >= hi) continue;

            const __nv_bfloat16* B = Ball + (size_t)e * N * K;

            float acc[4][8][4];
            #pragma unroll
            for (int mi = 0; mi < 4; ++mi)
                #pragma unroll
                for (int ni = 0; ni < 8; ++ni)
                    #pragma unroll
                    for (int r = 0; r < 4; ++r) acc[mi][ni][r] = 0.f;

            // loader: 256 rows x 8 16B-chunks = 2048 chunks, 16 per thread
            auto load_stage = [&](int s, int kt) {
                char* sA = smem + s * STAGE_BYTES;
                char* sB = sA + A_BYTES;
                int c = tid;
                #pragma unroll
                for (int i = 0; i < 8; ++i, c += 128) {      // A: 1024 chunks
                    const int row = c >> 3, cc = c & 7;
                    cp16(smem_u32(sA + row * ROWB + cc * 16),
                         A + (size_t)(m0 + row) * K + kt * BK + cc * 8);
                }
                c = tid;
                #pragma unroll
                for (int i = 0; i < 8; ++i, c += 128) {      // B: 1024 chunks
                    const int row = c >> 3, cc = c & 7;
                    cp16(smem_u32(sB + row * ROWB + cc * 16),
                         B + (size_t)(n0 + row) * K + kt * BK + cc * 8);
                }
            };

            __syncthreads();   // smem free of previous tile/segment readers

            #pragma unroll
            for (int s = 0; s < STAGES - 1; ++s) {
                if (s < nk) load_stage(s, s);
                cp_commit();
            }

            for (int kt = 0; kt < nk; ++kt) {
                cp_wait<STAGES - 2>();
                __syncthreads();

                const int nkt = kt + STAGES - 1;
                if (nkt < nk) load_stage(nkt % STAGES, nkt);
                cp_commit();

                const int s = kt % STAGES;
                const uint32_t aS = sbase + s * STAGE_BYTES;
                const uint32_t bS = aS + A_BYTES;

                #pragma unroll
                for (int ks = 0; ks < BK / 16; ++ks) {
                    const int kk = ks * 32;  // bytes
                    uint32_t a[4][4];
                    #pragma unroll
                    for (int mi = 0; mi < 4; ++mi)
                        ldsm_x4(a[mi], aS + (wm + mi * 16 + fr) * ROWB + kk + fc);
                    uint32_t b[4][4];
                    #pragma unroll
                    for (int nj = 0; nj < 4; ++nj)
                        ldsm_x4(b[nj], bS + (wn + nj * 16 + fr) * ROWB + kk + fc);
                    #pragma unroll
                    for (int mi = 0; mi < 4; ++mi)
                        #pragma unroll
                        for (int n8 = 0; n8 < 8; ++n8) {
                            const uint32_t b0 = b[n8 >> 1][n8 & 1];
                            const uint32_t b1 = b[n8 >> 1][(n8 & 1) + 2];
                            asm volatile(
                                "mma.sync.aligned.m16n8k16.row.col.f32.bf16.bf16.f32 "
                                "{%0,%1,%2,%3}, {%4,%5,%6,%7}, {%8,%9}, {%0,%1,%2,%3};"
                                : "+f"(acc[mi][n8][0]), "+f"(acc[mi][n8][1]),
                                  "+f"(acc[mi][n8][2]), "+f"(acc[mi][n8][3])
                                : "r"(a[mi][0]), "r"(a[mi][1]), "r"(a[mi][2]), "r"(a[mi][3]),
                                  "r"(b0), "r"(b1));
                        }
                }
            }

            // Epilogue: bf16-round (reference keeps bf16 after each dot), masked.
            #pragma unroll
            for (int mi = 0; mi < 4; ++mi) {
                const int r0 = m0 + wm + mi * 16 + (lane >> 2);
                const int r1 = r0 + 8;
                const bool ok0 = (r0 >= lo) && (r0 < hi);
                const bool ok1 = (r1 >= lo) && (r1 < hi);
                #pragma unroll
                for (int n8 = 0; n8 < 8; ++n8) {
                    const int col = n0 + wn + n8 * 8 + (lane & 3) * 2;
                    if (ok0) {
                        if constexpr (sizeof(OT) == 2) {
                            __nv_bfloat162 v = __floats2bfloat162_rn(acc[mi][n8][0], acc[mi][n8][1]);
                            *reinterpret_cast<__nv_bfloat162*>(C + (size_t)r0 * N + col) = v;
                        } else {
                            float2 v = make_float2(
                                __bfloat162float(__float2bfloat16(acc[mi][n8][0])),
                                __bfloat162float(__float2bfloat16(acc[mi][n8][1])));
                            *reinterpret_cast<float2*>(C + (size_t)r0 * N + col) = v;
                        }
                    }
                    if (ok1) {
                        if constexpr (sizeof(OT) == 2) {
                            __nv_bfloat162 v = __floats2bfloat162_rn(acc[mi][n8][2], acc[mi][n8][3]);
                            *reinterpret_cast<__nv_bfloat162*>(C + (size_t)r1 * N + col) = v;
                        } else {
                            float2 v = make_float2(
                                __bfloat162float(__float2bfloat16(acc[mi][n8][2])),
                                __bfloat162float(__float2bfloat16(acc[mi][n8][3])));
                            *reinterpret_cast<float2*>(C + (size_t)r1 * N + col) = v;
                        }
                    }
                }
            }
        }
    }
}

extern "C" void kernel_launch(void* const* d_in, const int* in_sizes, int n_in,
                              void* d_out, int out_size) {
    const float* x      = (const float*)d_in[0];   // [TT, DIMC]
    const float* w1     = (const float*)d_in[1];   // [NEXP, HIDC, DIMC]
    const float* w2     = (const float*)d_in[2];   // [NEXP, DIMC, HIDC]
    const int*   counts = (const int*)d_in[3];     // [NEXP]
    float*       out    = (float*)d_out;           // [TT, DIMC]

    void *xb, *w1b, *w2b, *hb;
    cudaGetSymbolAddress(&xb,  g_xb);
    cudaGetSymbolAddress(&w1b, g_w1b);
    cudaGetSymbolAddress(&w2b, g_w2b);
    cudaGetSymbolAddress(&hb,  g_hidden);

    int sms = 148;
    cudaDeviceGetAttribute(&sms, cudaDevAttrMultiProcessorCount, 0);
    const int pgrid = 2 * sms;   // persistent grid (2 CTAs/SM)

    cudaFuncSetAttribute(gemm_grouped<__nv_bfloat16>,
                         cudaFuncAttributeMaxDynamicSharedMemorySize, SMEM_DYN);
    cudaFuncSetAttribute(gemm_grouped<float>,
                         cudaFuncAttributeMaxDynamicSharedMemorySize, SMEM_DYN);

    // fp32 -> bf16 conversions (one merged persistent kernel)
    {
        int nx = TT * DIMC / 4;
        int nw = NEXP * HIDC * DIMC / 4;
        cvt_all<<<4 * sms, 256>>>((const float4*)x,  (uint2*)xb,  nx,
                                  (const float4*)w1, (uint2*)w1b, nw,
                                  (const float4*)w2, (uint2*)w2b);
    }

    // GEMM1: hidden[T, HID] = x_bf16 @ w1[e]^T   (bf16 out)
    gemm_grouped<__nv_bfloat16><<<pgrid, 128, SMEM_DYN>>>(
        (const __nv_bfloat16*)xb, (const __nv_bfloat16*)w1b,
        (__nv_bfloat16*)hb, counts, DIMC, HIDC,
        TT / BM, (TT / BM) * (HIDC / BN));
    // GEMM2: out[T, DIM] = hidden @ w2[e]^T   (bf16-rounded fp32 out)
    gemm_grouped<float><<<pgrid, 128, SMEM_DYN>>>(
        (const __nv_bfloat16*)hb, (const __nv_bfloat16*)w2b,
        out, counts, HIDC, DIMC,
        TT / BM, (TT / BM) * (DIMC / BN));
}